// round 2
// baseline (speedup 1.0000x reference)
#include <cuda_runtime.h>
#include <cuda_bf16.h>

// MQCNN layer, closed form (see R0 derivation):
// z = (6cos(a) + cos(a+s1)+...+cos(a+s1+s2+s3+s4+s5)) / 16
// U3_w provably dead (unitaries on wire 6 preserve the wire-4 marginal).
//
// R1: pair-split. Two threads per output: lane parity p selects patch row
// (2j+p). Each thread makes 3 float2 loads (contiguous 128B per half-warp
// per load -> fully coalesced), exchanges 5 scalars via shfl.bfly, computes
// 6 of the 11 cosines, combines with one more shfl. Doubles resident warps
// (occupancy 34% -> ~75%) and halves the per-warp latency chain.

#define CH_STRIDE (128 * 128)
#define N_THREADS (32 * 64 * 64 * 2)   // 2 threads per output

__global__ __launch_bounds__(256) void mqcnn_kernel(
    const float* __restrict__ x, float* __restrict__ out)
{
    int tid = blockIdx.x * blockDim.x + threadIdx.x;
    int o = tid >> 1;          // output index
    int p = tid & 1;           // 0: row 2j, 1: row 2j+1

    int k = o & 63;
    int j = (o >> 6) & 63;
    int b = o >> 12;

    // this thread's row across 3 channels
    const float* base = x + (size_t)b * (3 * CH_STRIDE)
                          + (size_t)(2 * j + p) * 128 + 2 * k;
    float2 L0 = *reinterpret_cast<const float2*>(base);                 // ch0
    float2 L1 = *reinterpret_cast<const float2*>(base + CH_STRIDE);     // ch1
    float2 L2 = *reinterpret_cast<const float2*>(base + 2 * CH_STRIDE); // ch2

    bool pp = (p != 0);

    // p0 locals: a = sum of .x over channels; u1=c0r0.y u4=c1r0.y u5=c2r0.y
    // p1 locals: v1=c1r1.x s2=c0r1.x+c2r1.y s3=c0r1.y v4=c2r1.x v5=c1r1.y
    float a   = L0.x + L1.x + L2.x;   // meaningful on p0
    float u1  = L0.y;                 // p0
    float u4  = L1.y;                 // p0
    float u5  = L2.y;                 // p0
    float v1  = L1.x;                 // p1
    float s2l = L0.x + L2.y;          // p1
    float s3l = L0.y;                 // p1
    float v4  = L2.x;                 // p1
    float v5  = L1.y;                 // p1

    // exchange: 5 bfly shuffles, slot contents differ by parity
    const unsigned m = 0xFFFFFFFFu;
    float o0 = pp ? v1  : a;
    float o1 = pp ? s2l : u1;
    float o2 = pp ? s3l : u4;
    float o3 = pp ? v4  : u5;
    float o4 = v5;                    // p0's slot4 is a don't-care
    float r0 = __shfl_xor_sync(m, o0, 1);
    float r1 = __shfl_xor_sync(m, o1, 1);
    float r2 = __shfl_xor_sync(m, o2, 1);
    float r3 = __shfl_xor_sync(m, o3, 1);
    float r4 = __shfl_xor_sync(m, o4, 1);

    // reconstruct full (A, S1..S5) on both lanes
    float A  = pp ? r0 : a;
    float S1 = pp ? (v1 + r1) : (u1 + r0);
    float S2 = pp ? s2l : r1;
    float S3 = pp ? s3l : r2;
    float S4 = pp ? (v4 + r2) : (u4 + r3);
    float S5 = pp ? (v5 + r3) : (u5 + r4);

    // split the 11 cosines 6/5 across the pair (p1 gets a zero-weight 6th)
    float w0 = pp ? 1.0f : 6.0f;
    float e0 = pp ? (A + S2 + S3 + S4)           : A;
    float e1 = pp ? (A + S1 + S3)                : (A + S1);
    float e2 = pp ? (A + S2 + S5)                : (A + S2);
    float e3 = pp ? (A + S1 + S4 + S5)           : (A + S3);
    float e4 = pp ? (A + S1 + S2 + S3 + S4 + S5) : (A + S4);
    float w5 = pp ? 0.0f : 1.0f;
    float e5 = A + S5;

    float sum = w0 * __cosf(e0);
    sum += __cosf(e1);
    sum += __cosf(e2);
    sum += __cosf(e3);
    sum += __cosf(e4);
    sum += w5 * __cosf(e5);

    sum += __shfl_xor_sync(m, sum, 1);
    if (!pp) out[o] = sum * 0.0625f;
}

extern "C" void kernel_launch(void* const* d_in, const int* in_sizes, int n_in,
                              void* d_out, int out_size) {
    const float* x = (const float*)d_in[0];   // [32,3,128,128] float32
    float* out = (float*)d_out;               // [32,1,64,64] float32
    mqcnn_kernel<<<N_THREADS / 256, 256>>>(x, out);
}

// round 3
// speedup vs baseline: 1.0048x; 1.0048x over previous
#include <cuda_runtime.h>
#include <cuda_bf16.h>

// MQCNN layer, closed form (R0 derivation):
// z = (6cos(a) + cos(a+s1)+cos(a+s2)+cos(a+s3)+cos(a+s4)+cos(a+s5)
//    + cos(a+s1+s3)+cos(a+s2+s5)+cos(a+s2+s3+s4)+cos(a+s1+s4+s5)
//    + cos(a+s1+s2+s3+s4+s5)) / 16
// U3_w provably dead (unitaries on wire 6 preserve the wire-4 marginal).
//
// R2: 2 outputs per thread, float4 loads (6x LDG.128, independent/front-
// batched), float2 store. Halves warp-LDG count and amortizes addressing;
// no shfl machinery (R1 showed it buys nothing).

#define CH_STRIDE (128 * 128)
#define N_PAIRS (32 * 64 * 32)   // 65536 threads, 2 outputs each

__device__ __forceinline__ float eval_patch(
    float c0r0x, float c0r0y, float c0r1x, float c0r1y,
    float c1r0x, float c1r0y, float c1r1x, float c1r1y,
    float c2r0x, float c2r0y, float c2r1x, float c2r1y)
{
    float a  = c0r0x + c1r0x + c2r0x;
    float s1 = c0r0y + c1r1x;
    float s2 = c0r1x + c2r1y;
    float s3 = c0r1y;
    float s4 = c1r0y + c2r1x;
    float s5 = c1r1y + c2r0y;

    float s13 = s1 + s3;
    float s45 = s4 + s5;

    float sum = 6.0f * __cosf(a);
    sum += __cosf(a + s1);
    sum += __cosf(a + s2);
    sum += __cosf(a + s3);
    sum += __cosf(a + s4);
    sum += __cosf(a + s5);
    sum += __cosf(a + s13);
    sum += __cosf(a + s2 + s5);
    sum += __cosf(a + s2 + s3 + s4);
    sum += __cosf(a + s1 + s45);
    sum += __cosf(a + s13 + s2 + s45);
    return sum * 0.0625f;
}

__global__ __launch_bounds__(256) void mqcnn_kernel(
    const float* __restrict__ x, float* __restrict__ out)
{
    int tid = blockIdx.x * blockDim.x + threadIdx.x;

    int kp = tid & 31;          // pair index within row (covers cols 4kp..4kp+3)
    int j  = (tid >> 5) & 63;
    int b  = tid >> 11;

    const float* base = x + (size_t)b * (3 * CH_STRIDE)
                          + (size_t)(2 * j) * 128 + 4 * kp;

    // 6 independent 16B loads: rows 2j,2j+1 across 3 channels
    float4 c0r0 = *reinterpret_cast<const float4*>(base);
    float4 c0r1 = *reinterpret_cast<const float4*>(base + 128);
    float4 c1r0 = *reinterpret_cast<const float4*>(base + CH_STRIDE);
    float4 c1r1 = *reinterpret_cast<const float4*>(base + CH_STRIDE + 128);
    float4 c2r0 = *reinterpret_cast<const float4*>(base + 2 * CH_STRIDE);
    float4 c2r1 = *reinterpret_cast<const float4*>(base + 2 * CH_STRIDE + 128);

    float z0 = eval_patch(c0r0.x, c0r0.y, c0r1.x, c0r1.y,
                          c1r0.x, c1r0.y, c1r1.x, c1r1.y,
                          c2r0.x, c2r0.y, c2r1.x, c2r1.y);
    float z1 = eval_patch(c0r0.z, c0r0.w, c0r1.z, c0r1.w,
                          c1r0.z, c1r0.w, c1r1.z, c1r1.w,
                          c2r0.z, c2r0.w, c2r1.z, c2r1.w);

    int o = (b << 12) + (j << 6) + (kp << 1);
    *reinterpret_cast<float2*>(out + o) = make_float2(z0, z1);
}

extern "C" void kernel_launch(void* const* d_in, const int* in_sizes, int n_in,
                              void* d_out, int out_size) {
    const float* x = (const float*)d_in[0];   // [32,3,128,128] float32
    float* out = (float*)d_out;               // [32,1,64,64] float32
    mqcnn_kernel<<<N_PAIRS / 256, 256>>>(x, out);
}